// round 11
// baseline (speedup 1.0000x reference)
#include <cuda_runtime.h>
#include <math.h>

#define N_NODES 5000
#define E_EDGES 160000
#define F_HID   16

typedef unsigned long long ull;

// ---- scratch (device globals: no allocation allowed) ----
__device__ float g_inv[N_NODES];            // deg -> rsqrt(deg)
__device__ float g_h1 [N_NODES * F_HID];    // x @ W1  (red-accumulated over k-splits)
__device__ float g_a1 [N_NODES * F_HID];    // A_hat @ h1
__device__ float g_hr [N_NODES * F_HID];    // relu(a1 + b1)
__device__ float g_p2 [N_NODES * F_HID];    // A_hat @ hr

// ---------------- f32x2 / red / cp.async helpers ----------------
__device__ __forceinline__ ull ffma2(ull a, ull b, ull c) {
    ull d;
    asm("fma.rn.f32x2 %0, %1, %2, %3;" : "=l"(d) : "l"(a), "l"(b), "l"(c));
    return d;
}
__device__ __forceinline__ ull fpack(float lo, float hi) {
    ull r;
    asm("mov.b64 %0, {%1, %2};" : "=l"(r) : "f"(lo), "f"(hi));
    return r;
}
__device__ __forceinline__ float2 funpack(ull v) {
    float2 r;
    asm("mov.b64 {%0, %1}, %2;" : "=f"(r.x), "=f"(r.y) : "l"(v));
    return r;
}
__device__ __forceinline__ void red_add_v4(float* p, float a, float b, float c, float d) {
    asm volatile("red.global.add.v4.f32 [%0], {%1, %2, %3, %4};"
                 :: "l"(p), "f"(a), "f"(b), "f"(c), "f"(d) : "memory");
}
__device__ __forceinline__ void cp_async16(unsigned dst, const void* src, int src_bytes) {
    asm volatile("cp.async.cg.shared.global [%0], [%1], 16, %2;"
                 :: "r"(dst), "l"(src), "r"(src_bytes) : "memory");
}
__device__ __forceinline__ void cp_commit() {
    asm volatile("cp.async.commit_group;" ::: "memory");
}
template <int N>
__device__ __forceinline__ void cp_wait() {
    asm volatile("cp.async.wait_group %0;" :: "n"(N) : "memory");
}

// ---------------- init: zero g_h1, g_inv = 1 ----------------
__global__ void k_init() {
    int i = blockIdx.x * blockDim.x + threadIdx.x;
    if (i < N_NODES * F_HID) g_h1[i] = 0.0f;
    if (i < N_NODES) g_inv[i] = 1.0f;   // self loop counts 1
}

__global__ void k_deg_edges(const int* __restrict__ dst) {
    int e = blockIdx.x * blockDim.x + threadIdx.x;
    if (e < E_EDGES) atomicAdd(&g_inv[dst[e]], 1.0f);
}

__global__ void k_rsqrt() {
    int i = blockIdx.x * blockDim.x + threadIdx.x;
    if (i < N_NODES) g_inv[i] = rsqrtf(g_inv[i]);
}

// ---------------- GEMM1: g_h1 += x[N,N] @ W1[N,16] ----------------
// Block = 512 threads (16 warps), 1024 rows/block; each thread owns 2 full
// rows (t, t+512) -> NO cross-lane reduction. Accumulators are j-pairs
// (f32x2): acc[2][8] = 32 regs. W chunk broadcast via uniform LDS.128.
// x tile (1024 rows x 16 k, stride 20 words) staged with cp.async,
// double-buffered. K-split tuned to a SINGLE wave:
//   KR = 176 (11 chunks of 16), 29 splits x 5 row-groups = 145 blocks <= 148 SM.
#define G1_ROWS 1024
#define G1_KC   16
#define G1_KR   176
#define G1_NCH  (G1_KR / G1_KC)   // 11
#define G1_XSTR 20                // smem row stride (words), 16B-aligned

#define G1_XBUF (G1_ROWS * G1_XSTR)        // floats per x buffer (20480)
#define G1_WBUF (G1_KC * F_HID)            // floats per W buffer (256)
#define G1_SMEM ((2 * G1_XBUF + 2 * G1_WBUF) * 4)  // 165888 B

__global__ void __launch_bounds__(512) k_gemm1(const float* __restrict__ x,
                                               const float* __restrict__ W1) {
    extern __shared__ float smem[];
    const unsigned sbase = (unsigned)__cvta_generic_to_shared(smem);
    const int tid   = threadIdx.x;
    const int row0  = blockIdx.x * G1_ROWS;
    const int kbase = blockIdx.y * G1_KR;
    const int kend  = (kbase + G1_KR < N_NODES) ? kbase + G1_KR : N_NODES;

    // buffer offsets (floats): x0, x1, w0, w1
    const unsigned xoff[2] = { 0u, (unsigned)G1_XBUF };
    const unsigned woff[2] = { (unsigned)(2 * G1_XBUF),
                               (unsigned)(2 * G1_XBUF + G1_WBUF) };

    ull acc[2][8];
#pragma unroll
    for (int r = 0; r < 2; ++r)
#pragma unroll
        for (int j = 0; j < 8; ++j) acc[r][j] = 0ull;

    // ---- async stage of chunk ch into buffer b ----
    auto stage = [&](int ch, int b) {
        const int k0 = kbase + ch * G1_KC;
        // x: 4096 float4s, 8 per thread; lanes -> consecutive (row, c4)
#pragma unroll
        for (int i = 0; i < 8; ++i) {
            int idx  = tid + 512 * i;
            int lrow = idx >> 2, c4 = idx & 3;
            int grow = row0 + lrow; if (grow >= N_NODES) grow = N_NODES - 1;
            int gk   = k0 + c4 * 4;
            int ok   = (gk < kend);
            const float* src = x + (size_t)grow * N_NODES + (ok ? gk : 0);
            unsigned dst = sbase + (xoff[b] + lrow * G1_XSTR + c4 * 4) * 4u;
            cp_async16(dst, src, ok ? 16 : 0);
        }
        // W chunk: 16 rows x 64B = 64 float4s
        if (tid < 64) {
            int k = tid >> 2, c4 = tid & 3;
            int gk = k0 + k;
            int ok = (gk < kend);
            const float* src = W1 + (size_t)(ok ? gk : 0) * F_HID + c4 * 4;
            unsigned dst = sbase + (woff[b] + k * F_HID + c4 * 4) * 4u;
            cp_async16(dst, src, ok ? 16 : 0);
        }
        cp_commit();
    };

    stage(0, 0);

#pragma unroll
    for (int ch = 0; ch < G1_NCH; ++ch) {
        const int b = ch & 1;
        if (ch + 1 < G1_NCH) { stage(ch + 1, b ^ 1); cp_wait<1>(); }
        else                 { cp_wait<0>(); }
        __syncthreads();

        const float* sx = smem + xoff[b];
        const ull*   sw = (const ull*)(smem + woff[b]);

#pragma unroll
        for (int kq = 0; kq < 4; ++kq) {
            float4 xv[2];
#pragma unroll
            for (int rr = 0; rr < 2; ++rr)
                xv[rr] = *(const float4*)&sx[(tid + rr * 512) * G1_XSTR + kq * 4];
#pragma unroll
            for (int e = 0; e < 4; ++e) {
                const int k = kq * 4 + e;
                ulonglong2 w01 = *(const ulonglong2*)&sw[k * 8 + 0];
                ulonglong2 w23 = *(const ulonglong2*)&sw[k * 8 + 2];
                ulonglong2 w45 = *(const ulonglong2*)&sw[k * 8 + 4];
                ulonglong2 w67 = *(const ulonglong2*)&sw[k * 8 + 6];
#pragma unroll
                for (int rr = 0; rr < 2; ++rr) {
                    float xs = (e == 0) ? xv[rr].x : (e == 1) ? xv[rr].y
                             : (e == 2) ? xv[rr].z : xv[rr].w;
                    ull xd = fpack(xs, xs);
                    acc[rr][0] = ffma2(xd, w01.x, acc[rr][0]);
                    acc[rr][1] = ffma2(xd, w01.y, acc[rr][1]);
                    acc[rr][2] = ffma2(xd, w23.x, acc[rr][2]);
                    acc[rr][3] = ffma2(xd, w23.y, acc[rr][3]);
                    acc[rr][4] = ffma2(xd, w45.x, acc[rr][4]);
                    acc[rr][5] = ffma2(xd, w45.y, acc[rr][5]);
                    acc[rr][6] = ffma2(xd, w67.x, acc[rr][6]);
                    acc[rr][7] = ffma2(xd, w67.y, acc[rr][7]);
                }
            }
        }
        __syncthreads();
    }

    // epilogue: each thread owns 2 complete rows -> 4x red.v4 per row
#pragma unroll
    for (int rr = 0; rr < 2; ++rr) {
        int row = row0 + tid + rr * 512;
        if (row < N_NODES) {
            float* o = &g_h1[row * F_HID];
            float2 a0 = funpack(acc[rr][0]), a1 = funpack(acc[rr][1]);
            float2 a2 = funpack(acc[rr][2]), a3 = funpack(acc[rr][3]);
            float2 a4 = funpack(acc[rr][4]), a5 = funpack(acc[rr][5]);
            float2 a6 = funpack(acc[rr][6]), a7 = funpack(acc[rr][7]);
            red_add_v4(o + 0,  a0.x, a0.y, a1.x, a1.y);
            red_add_v4(o + 4,  a2.x, a2.y, a3.x, a3.y);
            red_add_v4(o + 8,  a4.x, a4.y, a5.x, a5.y);
            red_add_v4(o + 12, a6.x, a6.y, a7.x, a7.y);
        }
    }
}

// ---------------- 16-wide propagation (R4 proven versions) ----------------
__global__ void k_self1() {
    int t = blockIdx.x * blockDim.x + threadIdx.x;
    if (t >= N_NODES * 4) return;
    int i = t >> 2;
    float iv = g_inv[i], c = iv * iv;
    float4 v = *(const float4*)&g_h1[t * 4];
    v.x *= c; v.y *= c; v.z *= c; v.w *= c;
    *(float4*)&g_a1[t * 4] = v;
}

template <int L>
__global__ void k_edge_agg(const int* __restrict__ src, const int* __restrict__ dst) {
    int t = blockIdx.x * blockDim.x + threadIdx.x;
    if (t >= E_EDGES * 4) return;
    int e = t >> 2, q = t & 3;
    int s = __ldg(src + e), d = __ldg(dst + e);
    const float* feat  = (L == 1) ? g_h1 : g_hr;
    float*       accum = (L == 1) ? g_a1 : g_p2;
    float c = g_inv[s] * g_inv[d];
    float4 v = *(const float4*)&feat[s * F_HID + q * 4];
    float* a = &accum[d * F_HID + q * 4];
    atomicAdd(a + 0, v.x * c);
    atomicAdd(a + 1, v.y * c);
    atomicAdd(a + 2, v.z * c);
    atomicAdd(a + 3, v.w * c);
}

__global__ void k_relu_self2(const float* __restrict__ b1) {
    int t = blockIdx.x * blockDim.x + threadIdx.x;
    if (t >= N_NODES * 4) return;
    int i = t >> 2, q = t & 3;
    float iv = g_inv[i], c = iv * iv;
    float4 b = *(const float4*)&b1[q * 4];
    float4 h = *(const float4*)&g_a1[t * 4];
    h.x = fmaxf(h.x + b.x, 0.f); h.y = fmaxf(h.y + b.y, 0.f);
    h.z = fmaxf(h.z + b.z, 0.f); h.w = fmaxf(h.w + b.w, 0.f);
    *(float4*)&g_hr[t * 4] = h;
    float4 p = make_float4(h.x * c, h.y * c, h.z * c, h.w * c);
    *(float4*)&g_p2[t * 4] = p;
}

// ---------------- GEMM2 + bias + log_softmax, fused (R4 proven) ----------------
__global__ void __launch_bounds__(256) k_gemm2(const float* __restrict__ W2,
                                               const float* __restrict__ b2,
                                               float* __restrict__ out) {
    extern __shared__ float sZ[];        // [8][N_NODES] = 160000 B
    __shared__ ull sPp[4 * F_HID];       // packed row pairs of p2
    const int tid  = threadIdx.x;
    const int row0 = blockIdx.x * 8;

    if (tid < 4 * F_HID) {
        int pr = tid >> 4, k = tid & 15;
        sPp[tid] = fpack(g_p2[(row0 + 2 * pr) * F_HID + k],
                         g_p2[(row0 + 2 * pr + 1) * F_HID + k]);
    }
    __syncthreads();

    for (int c4 = tid; c4 < N_NODES / 4; c4 += 256) {
        const int c = c4 * 4;
        float4 bv = *(const float4*)&b2[c];
        ull bd0 = fpack(bv.x, bv.x), bd1 = fpack(bv.y, bv.y);
        ull bd2 = fpack(bv.z, bv.z), bd3 = fpack(bv.w, bv.w);
        ull acc[4][4];
#pragma unroll
        for (int pr = 0; pr < 4; ++pr) {
            acc[pr][0] = bd0; acc[pr][1] = bd1; acc[pr][2] = bd2; acc[pr][3] = bd3;
        }
#pragma unroll
        for (int k = 0; k < F_HID; ++k) {
            float4 w = *(const float4*)&W2[k * N_NODES + c];
            ull w0 = fpack(w.x, w.x), w1 = fpack(w.y, w.y);
            ull w2 = fpack(w.z, w.z), w3 = fpack(w.w, w.w);
#pragma unroll
            for (int pr = 0; pr < 4; ++pr) {
                ull pp = sPp[pr * F_HID + k];   // broadcast LDS.64
                acc[pr][0] = ffma2(pp, w0, acc[pr][0]);
                acc[pr][1] = ffma2(pp, w1, acc[pr][1]);
                acc[pr][2] = ffma2(pp, w2, acc[pr][2]);
                acc[pr][3] = ffma2(pp, w3, acc[pr][3]);
            }
        }
#pragma unroll
        for (int pr = 0; pr < 4; ++pr) {
            float2 a0 = funpack(acc[pr][0]), a1 = funpack(acc[pr][1]);
            float2 a2 = funpack(acc[pr][2]), a3 = funpack(acc[pr][3]);
            *(float4*)&sZ[(2 * pr)     * N_NODES + c] = make_float4(a0.x, a1.x, a2.x, a3.x);
            *(float4*)&sZ[(2 * pr + 1) * N_NODES + c] = make_float4(a0.y, a1.y, a2.y, a3.y);
        }
    }
    __syncthreads();

    const int warp = tid >> 5, lane = tid & 31;
    const float4* z4 = (const float4*)(sZ + warp * N_NODES);

    float m = -INFINITY;
    for (int i = lane; i < N_NODES / 4; i += 32) {
        float4 v = z4[i];
        m = fmaxf(m, fmaxf(fmaxf(v.x, v.y), fmaxf(v.z, v.w)));
    }
#pragma unroll
    for (int o = 16; o; o >>= 1) m = fmaxf(m, __shfl_xor_sync(0xffffffffu, m, o));

    float s = 0.0f;
    for (int i = lane; i < N_NODES / 4; i += 32) {
        float4 v = z4[i];
        s += __expf(v.x - m) + __expf(v.y - m) + __expf(v.z - m) + __expf(v.w - m);
    }
#pragma unroll
    for (int o = 16; o; o >>= 1) s += __shfl_xor_sync(0xffffffffu, s, o);

    float lse = m + logf(s);
    float4* orow = (float4*)(out + (size_t)(row0 + warp) * N_NODES);
    for (int i = lane; i < N_NODES / 4; i += 32) {
        float4 v = z4[i];
        orow[i] = make_float4(v.x - lse, v.y - lse, v.z - lse, v.w - lse);
    }
}

// ---------------- launch ----------------
extern "C" void kernel_launch(void* const* d_in, const int* in_sizes, int n_in,
                              void* d_out, int out_size) {
    const float* x   = (const float*)d_in[0];
    const int*   src = (const int*)  d_in[1];
    const int*   dst = (const int*)  d_in[2];
    const float* W1  = (const float*)d_in[3];
    const float* b1  = (const float*)d_in[4];
    const float* W2  = (const float*)d_in[5];
    const float* b2  = (const float*)d_in[6];
    float* out = (float*)d_out;

    const int smem2 = 8 * N_NODES * (int)sizeof(float);  // 160 KB
    cudaFuncSetAttribute(k_gemm2, cudaFuncAttributeMaxDynamicSharedMemorySize, smem2);
    cudaFuncSetAttribute(k_gemm1, cudaFuncAttributeMaxDynamicSharedMemorySize, G1_SMEM);

    k_init     <<<(N_NODES * F_HID + 255) / 256, 256>>>();
    k_deg_edges<<<(E_EDGES + 255) / 256, 256>>>(dst);
    k_rsqrt    <<<(N_NODES + 255) / 256, 256>>>();

    dim3 g1((N_NODES + G1_ROWS - 1) / G1_ROWS,      // 5
            (N_NODES + G1_KR - 1) / G1_KR);         // 29  -> 145 blocks, 1 wave
    k_gemm1<<<g1, 512, G1_SMEM>>>(x, W1);

    k_self1<<<(N_NODES * 4 + 255) / 256, 256>>>();
    k_edge_agg<1><<<(E_EDGES * 4 + 255) / 256, 256>>>(src, dst);

    k_relu_self2<<<(N_NODES * 4 + 255) / 256, 256>>>(b1);
    k_edge_agg<2><<<(E_EDGES * 4 + 255) / 256, 256>>>(src, dst);

    k_gemm2<<<N_NODES / 8, 256, smem2>>>(W2, b2, out);
}

// round 12
// speedup vs baseline: 1.0350x; 1.0350x over previous
#include <cuda_runtime.h>
#include <math.h>

#define N_NODES 5000
#define E_EDGES 160000
#define F_HID   16

typedef unsigned long long ull;

// ---- scratch (device globals: no allocation allowed) ----
__device__ float g_inv[N_NODES];            // deg -> rsqrt(deg)
__device__ float g_h1 [N_NODES * F_HID];    // x @ W1  (red-accumulated over k-splits)
__device__ float g_a1 [N_NODES * F_HID];    // A_hat @ h1
__device__ float g_hr [N_NODES * F_HID];    // relu(a1 + b1)
__device__ float g_p2 [N_NODES * F_HID];    // A_hat @ hr

// ---------------- f32x2 / red / cp.async helpers ----------------
__device__ __forceinline__ ull ffma2(ull a, ull b, ull c) {
    ull d;
    asm("fma.rn.f32x2 %0, %1, %2, %3;" : "=l"(d) : "l"(a), "l"(b), "l"(c));
    return d;
}
__device__ __forceinline__ ull fpack(float lo, float hi) {
    ull r;
    asm("mov.b64 %0, {%1, %2};" : "=l"(r) : "f"(lo), "f"(hi));
    return r;
}
__device__ __forceinline__ float2 funpack(ull v) {
    float2 r;
    asm("mov.b64 {%0, %1}, %2;" : "=f"(r.x), "=f"(r.y) : "l"(v));
    return r;
}
__device__ __forceinline__ void red_add_v4(float* p, float a, float b, float c, float d) {
    asm volatile("red.global.add.v4.f32 [%0], {%1, %2, %3, %4};"
                 :: "l"(p), "f"(a), "f"(b), "f"(c), "f"(d) : "memory");
}
__device__ __forceinline__ void cp_async16(unsigned dst, const void* src, int src_bytes) {
    asm volatile("cp.async.cg.shared.global [%0], [%1], 16, %2;"
                 :: "r"(dst), "l"(src), "r"(src_bytes) : "memory");
}
__device__ __forceinline__ void cp_commit() {
    asm volatile("cp.async.commit_group;" ::: "memory");
}
template <int N>
__device__ __forceinline__ void cp_wait() {
    asm volatile("cp.async.wait_group %0;" :: "n"(N) : "memory");
}

// ---------------- init: zero g_h1, g_inv = 1 ----------------
__global__ void k_init() {
    int i = blockIdx.x * blockDim.x + threadIdx.x;
    if (i < N_NODES * F_HID) g_h1[i] = 0.0f;
    if (i < N_NODES) g_inv[i] = 1.0f;   // self loop counts 1
}

__global__ void k_deg_edges(const int* __restrict__ dst) {
    int e = blockIdx.x * blockDim.x + threadIdx.x;
    if (e < E_EDGES) atomicAdd(&g_inv[dst[e]], 1.0f);
}

__global__ void k_rsqrt() {
    int i = blockIdx.x * blockDim.x + threadIdx.x;
    if (i < N_NODES) g_inv[i] = rsqrtf(g_inv[i]);
}

// ---------------- GEMM1: g_h1 += x[N,N] @ W1[N,16] ----------------
// Block = 512 threads (16 warps), 1024 rows/block; each thread owns 2 full
// rows (t, t+512) -> NO cross-lane reduction. Accumulators are j-pairs
// (f32x2): acc[2][8] = 32 regs. W chunk broadcast via uniform LDS.128.
// x tile (1024 rows x 16 k, stride 20 words) staged with cp.async,
// double-buffered. K-split tuned to a SINGLE wave:
//   KR = 176 (11 chunks of 16), 29 splits x 5 row-groups = 145 blocks <= 148 SM.
#define G1_ROWS 1024
#define G1_KC   16
#define G1_KR   176
#define G1_NCH  (G1_KR / G1_KC)   // 11
#define G1_XSTR 20                // smem row stride (words), 16B-aligned

#define G1_XBUF (G1_ROWS * G1_XSTR)        // floats per x buffer (20480)
#define G1_WBUF (G1_KC * F_HID)            // floats per W buffer (256)
#define G1_SMEM ((2 * G1_XBUF + 2 * G1_WBUF) * 4)  // 165888 B

__global__ void __launch_bounds__(512) k_gemm1(const float* __restrict__ x,
                                               const float* __restrict__ W1) {
    extern __shared__ float smem[];
    const unsigned sbase = (unsigned)__cvta_generic_to_shared(smem);
    const int tid   = threadIdx.x;
    const int row0  = blockIdx.x * G1_ROWS;
    const int kbase = blockIdx.y * G1_KR;
    const int kend  = (kbase + G1_KR < N_NODES) ? kbase + G1_KR : N_NODES;

    // buffer offsets (floats): x0, x1, w0, w1
    const unsigned xoff[2] = { 0u, (unsigned)G1_XBUF };
    const unsigned woff[2] = { (unsigned)(2 * G1_XBUF),
                               (unsigned)(2 * G1_XBUF + G1_WBUF) };

    ull acc[2][8];
#pragma unroll
    for (int r = 0; r < 2; ++r)
#pragma unroll
        for (int j = 0; j < 8; ++j) acc[r][j] = 0ull;

    // ---- async stage of chunk ch into buffer b ----
    auto stage = [&](int ch, int b) {
        const int k0 = kbase + ch * G1_KC;
        // x: 4096 float4s, 8 per thread; lanes -> consecutive (row, c4)
#pragma unroll
        for (int i = 0; i < 8; ++i) {
            int idx  = tid + 512 * i;
            int lrow = idx >> 2, c4 = idx & 3;
            int grow = row0 + lrow; if (grow >= N_NODES) grow = N_NODES - 1;
            int gk   = k0 + c4 * 4;
            int ok   = (gk < kend);
            const float* src = x + (size_t)grow * N_NODES + (ok ? gk : 0);
            unsigned dst = sbase + (xoff[b] + lrow * G1_XSTR + c4 * 4) * 4u;
            cp_async16(dst, src, ok ? 16 : 0);
        }
        // W chunk: 16 rows x 64B = 64 float4s
        if (tid < 64) {
            int k = tid >> 2, c4 = tid & 3;
            int gk = k0 + k;
            int ok = (gk < kend);
            const float* src = W1 + (size_t)(ok ? gk : 0) * F_HID + c4 * 4;
            unsigned dst = sbase + (woff[b] + k * F_HID + c4 * 4) * 4u;
            cp_async16(dst, src, ok ? 16 : 0);
        }
        cp_commit();
    };

    stage(0, 0);

#pragma unroll
    for (int ch = 0; ch < G1_NCH; ++ch) {
        const int b = ch & 1;
        if (ch + 1 < G1_NCH) { stage(ch + 1, b ^ 1); cp_wait<1>(); }
        else                 { cp_wait<0>(); }
        __syncthreads();

        const float* sx = smem + xoff[b];
        const ull*   sw = (const ull*)(smem + woff[b]);

#pragma unroll
        for (int kq = 0; kq < 4; ++kq) {
            float4 xv[2];
#pragma unroll
            for (int rr = 0; rr < 2; ++rr)
                xv[rr] = *(const float4*)&sx[(tid + rr * 512) * G1_XSTR + kq * 4];
#pragma unroll
            for (int e = 0; e < 4; ++e) {
                const int k = kq * 4 + e;
                ulonglong2 w01 = *(const ulonglong2*)&sw[k * 8 + 0];
                ulonglong2 w23 = *(const ulonglong2*)&sw[k * 8 + 2];
                ulonglong2 w45 = *(const ulonglong2*)&sw[k * 8 + 4];
                ulonglong2 w67 = *(const ulonglong2*)&sw[k * 8 + 6];
#pragma unroll
                for (int rr = 0; rr < 2; ++rr) {
                    float xs = (e == 0) ? xv[rr].x : (e == 1) ? xv[rr].y
                             : (e == 2) ? xv[rr].z : xv[rr].w;
                    ull xd = fpack(xs, xs);
                    acc[rr][0] = ffma2(xd, w01.x, acc[rr][0]);
                    acc[rr][1] = ffma2(xd, w01.y, acc[rr][1]);
                    acc[rr][2] = ffma2(xd, w23.x, acc[rr][2]);
                    acc[rr][3] = ffma2(xd, w23.y, acc[rr][3]);
                    acc[rr][4] = ffma2(xd, w45.x, acc[rr][4]);
                    acc[rr][5] = ffma2(xd, w45.y, acc[rr][5]);
                    acc[rr][6] = ffma2(xd, w67.x, acc[rr][6]);
                    acc[rr][7] = ffma2(xd, w67.y, acc[rr][7]);
                }
            }
        }
        __syncthreads();
    }

    // epilogue: each thread owns 2 complete rows -> 4x red.v4 per row
#pragma unroll
    for (int rr = 0; rr < 2; ++rr) {
        int row = row0 + tid + rr * 512;
        if (row < N_NODES) {
            float* o = &g_h1[row * F_HID];
            float2 a0 = funpack(acc[rr][0]), a1 = funpack(acc[rr][1]);
            float2 a2 = funpack(acc[rr][2]), a3 = funpack(acc[rr][3]);
            float2 a4 = funpack(acc[rr][4]), a5 = funpack(acc[rr][5]);
            float2 a6 = funpack(acc[rr][6]), a7 = funpack(acc[rr][7]);
            red_add_v4(o + 0,  a0.x, a0.y, a1.x, a1.y);
            red_add_v4(o + 4,  a2.x, a2.y, a3.x, a3.y);
            red_add_v4(o + 8,  a4.x, a4.y, a5.x, a5.y);
            red_add_v4(o + 12, a6.x, a6.y, a7.x, a7.y);
        }
    }
}

// ---------------- 16-wide propagation (R4 proven versions) ----------------
__global__ void k_self1() {
    int t = blockIdx.x * blockDim.x + threadIdx.x;
    if (t >= N_NODES * 4) return;
    int i = t >> 2;
    float iv = g_inv[i], c = iv * iv;
    float4 v = *(const float4*)&g_h1[t * 4];
    v.x *= c; v.y *= c; v.z *= c; v.w *= c;
    *(float4*)&g_a1[t * 4] = v;
}

template <int L>
__global__ void k_edge_agg(const int* __restrict__ src, const int* __restrict__ dst) {
    int t = blockIdx.x * blockDim.x + threadIdx.x;
    if (t >= E_EDGES * 4) return;
    int e = t >> 2, q = t & 3;
    int s = __ldg(src + e), d = __ldg(dst + e);
    const float* feat  = (L == 1) ? g_h1 : g_hr;
    float*       accum = (L == 1) ? g_a1 : g_p2;
    float c = g_inv[s] * g_inv[d];
    float4 v = *(const float4*)&feat[s * F_HID + q * 4];
    float* a = &accum[d * F_HID + q * 4];
    atomicAdd(a + 0, v.x * c);
    atomicAdd(a + 1, v.y * c);
    atomicAdd(a + 2, v.z * c);
    atomicAdd(a + 3, v.w * c);
}

__global__ void k_relu_self2(const float* __restrict__ b1) {
    int t = blockIdx.x * blockDim.x + threadIdx.x;
    if (t >= N_NODES * 4) return;
    int i = t >> 2, q = t & 3;
    float iv = g_inv[i], c = iv * iv;
    float4 b = *(const float4*)&b1[q * 4];
    float4 h = *(const float4*)&g_a1[t * 4];
    h.x = fmaxf(h.x + b.x, 0.f); h.y = fmaxf(h.y + b.y, 0.f);
    h.z = fmaxf(h.z + b.z, 0.f); h.w = fmaxf(h.w + b.w, 0.f);
    *(float4*)&g_hr[t * 4] = h;
    float4 p = make_float4(h.x * c, h.y * c, h.z * c, h.w * c);
    *(float4*)&g_p2[t * 4] = p;
}

// ---------------- GEMM2 + bias + log_softmax, fused (R4 proven) ----------------
__global__ void __launch_bounds__(256) k_gemm2(const float* __restrict__ W2,
                                               const float* __restrict__ b2,
                                               float* __restrict__ out) {
    extern __shared__ float sZ[];        // [8][N_NODES] = 160000 B
    __shared__ ull sPp[4 * F_HID];       // packed row pairs of p2
    const int tid  = threadIdx.x;
    const int row0 = blockIdx.x * 8;

    if (tid < 4 * F_HID) {
        int pr = tid >> 4, k = tid & 15;
        sPp[tid] = fpack(g_p2[(row0 + 2 * pr) * F_HID + k],
                         g_p2[(row0 + 2 * pr + 1) * F_HID + k]);
    }
    __syncthreads();

    for (int c4 = tid; c4 < N_NODES / 4; c4 += 256) {
        const int c = c4 * 4;
        float4 bv = *(const float4*)&b2[c];
        ull bd0 = fpack(bv.x, bv.x), bd1 = fpack(bv.y, bv.y);
        ull bd2 = fpack(bv.z, bv.z), bd3 = fpack(bv.w, bv.w);
        ull acc[4][4];
#pragma unroll
        for (int pr = 0; pr < 4; ++pr) {
            acc[pr][0] = bd0; acc[pr][1] = bd1; acc[pr][2] = bd2; acc[pr][3] = bd3;
        }
#pragma unroll
        for (int k = 0; k < F_HID; ++k) {
            float4 w = *(const float4*)&W2[k * N_NODES + c];
            ull w0 = fpack(w.x, w.x), w1 = fpack(w.y, w.y);
            ull w2 = fpack(w.z, w.z), w3 = fpack(w.w, w.w);
#pragma unroll
            for (int pr = 0; pr < 4; ++pr) {
                ull pp = sPp[pr * F_HID + k];   // broadcast LDS.64
                acc[pr][0] = ffma2(pp, w0, acc[pr][0]);
                acc[pr][1] = ffma2(pp, w1, acc[pr][1]);
                acc[pr][2] = ffma2(pp, w2, acc[pr][2]);
                acc[pr][3] = ffma2(pp, w3, acc[pr][3]);
            }
        }
#pragma unroll
        for (int pr = 0; pr < 4; ++pr) {
            float2 a0 = funpack(acc[pr][0]), a1 = funpack(acc[pr][1]);
            float2 a2 = funpack(acc[pr][2]), a3 = funpack(acc[pr][3]);
            *(float4*)&sZ[(2 * pr)     * N_NODES + c] = make_float4(a0.x, a1.x, a2.x, a3.x);
            *(float4*)&sZ[(2 * pr + 1) * N_NODES + c] = make_float4(a0.y, a1.y, a2.y, a3.y);
        }
    }
    __syncthreads();

    const int warp = tid >> 5, lane = tid & 31;
    const float4* z4 = (const float4*)(sZ + warp * N_NODES);

    float m = -INFINITY;
    for (int i = lane; i < N_NODES / 4; i += 32) {
        float4 v = z4[i];
        m = fmaxf(m, fmaxf(fmaxf(v.x, v.y), fmaxf(v.z, v.w)));
    }
#pragma unroll
    for (int o = 16; o; o >>= 1) m = fmaxf(m, __shfl_xor_sync(0xffffffffu, m, o));

    float s = 0.0f;
    for (int i = lane; i < N_NODES / 4; i += 32) {
        float4 v = z4[i];
        s += __expf(v.x - m) + __expf(v.y - m) + __expf(v.z - m) + __expf(v.w - m);
    }
#pragma unroll
    for (int o = 16; o; o >>= 1) s += __shfl_xor_sync(0xffffffffu, s, o);

    float lse = m + logf(s);
    float4* orow = (float4*)(out + (size_t)(row0 + warp) * N_NODES);
    for (int i = lane; i < N_NODES / 4; i += 32) {
        float4 v = z4[i];
        orow[i] = make_float4(v.x - lse, v.y - lse, v.z - lse, v.w - lse);
    }
}

// ---------------- launch ----------------
extern "C" void kernel_launch(void* const* d_in, const int* in_sizes, int n_in,
                              void* d_out, int out_size) {
    const float* x   = (const float*)d_in[0];
    const int*   src = (const int*)  d_in[1];
    const int*   dst = (const int*)  d_in[2];
    const float* W1  = (const float*)d_in[3];
    const float* b1  = (const float*)d_in[4];
    const float* W2  = (const float*)d_in[5];
    const float* b2  = (const float*)d_in[6];
    float* out = (float*)d_out;

    const int smem2 = 8 * N_NODES * (int)sizeof(float);  // 160 KB
    cudaFuncSetAttribute(k_gemm2, cudaFuncAttributeMaxDynamicSharedMemorySize, smem2);
    cudaFuncSetAttribute(k_gemm1, cudaFuncAttributeMaxDynamicSharedMemorySize, G1_SMEM);

    k_init     <<<(N_NODES * F_HID + 255) / 256, 256>>>();
    k_deg_edges<<<(E_EDGES + 255) / 256, 256>>>(dst);
    k_rsqrt    <<<(N_NODES + 255) / 256, 256>>>();

    dim3 g1((N_NODES + G1_ROWS - 1) / G1_ROWS,      // 5
            (N_NODES + G1_KR - 1) / G1_KR);         // 29  -> 145 blocks, 1 wave
    k_gemm1<<<g1, 512, G1_SMEM>>>(x, W1);

    k_self1<<<(N_NODES * 4 + 255) / 256, 256>>>();
    k_edge_agg<1><<<(E_EDGES * 4 + 255) / 256, 256>>>(src, dst);

    k_relu_self2<<<(N_NODES * 4 + 255) / 256, 256>>>(b1);
    k_edge_agg<2><<<(E_EDGES * 4 + 255) / 256, 256>>>(src, dst);

    k_gemm2<<<N_NODES / 8, 256, smem2>>>(W2, b2, out);
}